// round 3
// baseline (speedup 1.0000x reference)
#include <cuda_runtime.h>
#include <math.h>

#define NTOT    16384
#define TLEN    41
#define NSTEP   40
#define THREADS 512
#define PPB     128          // particles per block (4 threads / particle)
#define BLOCKS  128

// ---- smem float offsets (weights k-major: adjacent j contiguous) ----
#define OFF_WIN  0                      // [24k][80j]
#define OFF_BIN  (OFF_WIN + 24*80)      // [80]
#define OFF_WH   (OFF_BIN + 80)         // [4l][80k][80j]
#define OFF_BH   (OFF_WH + 4*6400)      // [4][80]
#define OFF_WOUT (OFF_BH + 320)         // [80k][20j]
#define OFF_BOUT (OFF_WOUT + 1600)      // [20]
#define OFF_U    (OFF_BOUT + 20)        // [40][4] t-MLP table
#define OFF_Y    (OFF_U + 160)          // [20][128] particle state
#define OFF_HA   (OFF_Y + 20*128)       // [80][128] activations A
#define OFF_HB   (OFF_HA + 80*128)      // [80][128] activations B
#define SMEM_FLOATS (OFF_HB + 80*128)   // 52740 floats = 210960 B

typedef unsigned long long u64;

// packed f32x2 FMA (sm_100+): d = a*b + c per 32-bit lane
#define FMA2(d, a, b, c) \
    asm("fma.rn.f32x2 %0, %1, %2, %3;" : "=l"(d) : "l"(a), "l"(b), "l"(c))
#define PACK2(d, f) do { unsigned int _u = __float_as_uint(f); \
    asm("mov.b64 %0, {%1, %2};" : "=l"(d) : "r"(_u), "r"(_u)); } while (0)
#define UNPACK2(lo, hi, s) do { unsigned int _a, _b; \
    asm("mov.b64 {%0, %1}, %2;" : "=r"(_a), "=r"(_b) : "l"(s)); \
    lo = __uint_as_float(_a); hi = __uint_as_float(_b); } while (0)
#define TANHA(d, x) asm("tanh.approx.f32 %0, %1;" : "=f"(d) : "f"(x))

extern __shared__ float smem[];

__global__ void __launch_bounds__(THREADS, 1)
sde_kernel(const float* __restrict__ z, const float* __restrict__ t,
           const float* __restrict__ Tx, const float* __restrict__ noise,
           const float* __restrict__ tw_in, const float* __restrict__ tb_in,
           const float* __restrict__ tw_h,  const float* __restrict__ tb_h,
           const float* __restrict__ tw_out,const float* __restrict__ tb_out,
           const float* __restrict__ dw_in, const float* __restrict__ db_in,
           const float* __restrict__ dw_h,  const float* __restrict__ db_h,
           const float* __restrict__ dw_out,const float* __restrict__ db_out,
           float* __restrict__ ys, float* __restrict__ lqout) {
    float* s_win  = smem + OFF_WIN;
    float* s_bin  = smem + OFF_BIN;
    float* s_wh   = smem + OFF_WH;
    float* s_bh   = smem + OFF_BH;
    float* s_wout = smem + OFF_WOUT;
    float* s_bout = smem + OFF_BOUT;
    float* s_u    = smem + OFF_U;
    float* s_y    = smem + OFF_Y;
    float* s_hA   = smem + OFF_HA;
    float* s_hB   = smem + OFF_HB;

    const int tid = threadIdx.x;
    const int jg  = tid & 3;        // j-group (0..3): outputs [20jg, 20jg+20)
    const int pl  = tid >> 2;       // particle within block (0..127)

    // ---- cooperative load + transpose of drift weights into smem ----
    for (int idx = tid; idx < 24 * 80; idx += THREADS) {
        int j = idx / 24, k = idx % 24;
        s_win[k * 80 + j] = dw_in[idx];
    }
    for (int idx = tid; idx < 4 * 6400; idx += THREADS) {
        int l = idx / 6400, r = idx % 6400, j = r / 80, k = r % 80;
        s_wh[l * 6400 + k * 80 + j] = dw_h[idx];
    }
    for (int idx = tid; idx < 20 * 80; idx += THREADS) {
        int j = idx / 80, k = idx % 80;
        s_wout[k * 20 + j] = dw_out[idx];
    }
    if (tid < 80)              s_bin[tid]       = db_in[tid];
    if (tid >= 128 && tid < 448) s_bh[tid - 128] = db_h[tid - 128];
    if (tid >= 448 && tid < 468) s_bout[tid - 448] = db_out[tid - 448];

    // ---- t-MLP fused: thread i (<40) computes u(t_i) -> s_u ----
    if (tid >= 512 - 64 && tid < 512 - 64 + NSTEP) {
        int i = tid - (512 - 64);
        float ti = t[i];
        float h[20], h2[20];
#pragma unroll
        for (int j = 0; j < 20; j++) h[j] = fmaxf(tw_in[j] * ti + tb_in[j], 0.f);
        for (int l = 0; l < 4; l++) {
            const float* w = tw_h + l * 400;
            const float* b = tb_h + l * 20;
#pragma unroll
            for (int j = 0; j < 20; j++) {
                float a = b[j];
#pragma unroll
                for (int k = 0; k < 20; k++) a += w[j * 20 + k] * h[k];
                h2[j] = fmaxf(a, 0.f);
            }
#pragma unroll
            for (int j = 0; j < 20; j++) h[j] = h2[j];
        }
#pragma unroll
        for (int c = 0; c < 4; c++) {
            float a = tb_out[c];
#pragma unroll
            for (int k = 0; k < 20; k++) a += tw_out[c * 20 + k] * h[k];
            s_u[i * 4 + c] = a;
        }
    }
    __syncthreads();

    const int n = blockIdx.x * PPB + pl;
    const float Tval = Tx[n >> 6];
    const float dt  = t[1] - t[0];
    const float sdt = sqrtf(dt);
    const int cw = (pl + 8 * jg) & 127;   // swizzled activation column for writes

    // ---- particle state: this thread owns y[5jg .. 5jg+5) ----
    float yo[5];
    {
        const float* zp = z + (size_t)n * 20 + 5 * jg;
        float* y0 = ys + (size_t)n * 20 + 5 * jg;
#pragma unroll
        for (int i = 0; i < 5; i++) {
            yo[i] = zp[i];
            y0[i] = yo[i];
            s_y[(5 * jg + i) * 128 + pl] = yo[i];
        }
        if (jg == 0 && n >= 40 && (n - 40) % 41 == 0) lqout[(n - 40) / 41] = 0.f;
    }
    float lq = 0.f;
    __syncwarp();

    for (int step = 0; step < NSTEP; step++) {
        float ut[4];
#pragma unroll
        for (int c = 0; c < 4; c++) ut[c] = s_u[step * 4 + c] * Tval;

        // ======== input layer: [y(20), ut(4)] -> outputs [20jg,20jg+20), relu
        {
            u64 acc[10];
            const ulonglong2* bv = (const ulonglong2*)(s_bin + 20 * jg);
#pragma unroll
            for (int q = 0; q < 5; q++) { ulonglong2 b = bv[q]; acc[2*q] = b.x; acc[2*q+1] = b.y; }
#pragma unroll
            for (int k = 0; k < 24; k++) {
                float xv = (k < 20) ? s_y[k * 128 + pl] : ut[k - 20];
                u64 x2; PACK2(x2, xv);
                const ulonglong2* w = (const ulonglong2*)(s_win + k * 80 + 20 * jg);
#pragma unroll
                for (int q = 0; q < 5; q++) {
                    ulonglong2 wv = w[q];
                    FMA2(acc[2*q],   wv.x, x2, acc[2*q]);
                    FMA2(acc[2*q+1], wv.y, x2, acc[2*q+1]);
                }
            }
            float* hw = s_hA + (20 * jg) * 128 + cw;
#pragma unroll
            for (int q = 0; q < 10; q++) {
                float a, b; UNPACK2(a, b, acc[q]);
                hw[(2*q)   * 128] = fmaxf(a, 0.f);
                hw[(2*q+1) * 128] = fmaxf(b, 0.f);
            }
        }
        __syncwarp();

        // ======== 4 hidden layers 80 -> 80, tanh.approx ========
        float* hin  = s_hA;
        float* hout = s_hB;
        for (int l = 0; l < 4; l++) {
            const float* wl = s_wh + l * 6400 + 20 * jg;
            u64 acc[10];
            const ulonglong2* bv = (const ulonglong2*)(s_bh + l * 80 + 20 * jg);
#pragma unroll
            for (int q = 0; q < 5; q++) { ulonglong2 b = bv[q]; acc[2*q] = b.x; acc[2*q+1] = b.y; }
#pragma unroll
            for (int kc = 0; kc < 4; kc++) {
                const float* hr = hin + kc * 20 * 128 + ((pl + 8 * kc) & 127);
#pragma unroll
                for (int kk = 0; kk < 20; kk++) {
                    float hk = hr[kk * 128];
                    u64 h2; PACK2(h2, hk);
                    const ulonglong2* w = (const ulonglong2*)(wl + (kc * 20 + kk) * 80);
#pragma unroll
                    for (int q = 0; q < 5; q++) {
                        ulonglong2 wv = w[q];
                        FMA2(acc[2*q],   wv.x, h2, acc[2*q]);
                        FMA2(acc[2*q+1], wv.y, h2, acc[2*q+1]);
                    }
                }
            }
            float* hw = hout + (20 * jg) * 128 + cw;
#pragma unroll
            for (int q = 0; q < 10; q++) {
                float a, b; UNPACK2(a, b, acc[q]);
                TANHA(a, a); TANHA(b, b);
                hw[(2*q)   * 128] = a;
                hw[(2*q+1) * 128] = b;
            }
            __syncwarp();
            float* tmp = hin; hin = hout; hout = tmp;
        }
        // final hidden is in hin (== s_hA after 4 swaps)

        // ---- prefetch noise (own 5 lanes) ----
        float nz[5];
        {
            const float* np_ = noise + ((size_t)step * NTOT + n) * 22 + 5 * jg;
#pragma unroll
            for (int i = 0; i < 5; i++) nz[i] = __ldg(np_ + i);
        }

        // ======== output layer 80 -> 20, k-split over the quad ========
        float o[20];
        {
            u64 oc[10];
            const ulonglong2* bv = (const ulonglong2*)s_bout;
#pragma unroll
            for (int q = 0; q < 5; q++) {
                ulonglong2 b = bv[q];
                oc[2*q]   = (jg == 0) ? b.x : 0ull;
                oc[2*q+1] = (jg == 0) ? b.y : 0ull;
            }
            const float* hr = hin + (20 * jg) * 128 + cw;   // k in [20jg,20jg+20)
#pragma unroll
            for (int kk = 0; kk < 20; kk++) {
                float hk = hr[kk * 128];
                u64 h2; PACK2(h2, hk);
                const ulonglong2* w = (const ulonglong2*)(s_wout + (20 * jg + kk) * 20);
#pragma unroll
                for (int q = 0; q < 5; q++) {
                    ulonglong2 wv = w[q];
                    FMA2(oc[2*q],   wv.x, h2, oc[2*q]);
                    FMA2(oc[2*q+1], wv.y, h2, oc[2*q+1]);
                }
            }
#pragma unroll
            for (int q = 0; q < 10; q++) UNPACK2(o[2*q], o[2*q+1], oc[q]);
            // quad butterfly: sum partials over the 4 lanes of this particle
#pragma unroll
            for (int j = 0; j < 20; j++) {
                o[j] += __shfl_xor_sync(0xffffffffu, o[j], 1);
                o[j] += __shfl_xor_sync(0xffffffffu, o[j], 2);
            }
        }

        // ======== SDE update (own d-range [5jg, 5jg+5)) ========
        // h = theta*(mu-y) = -y ; f = o + y ; uu = 2*(o + 2y)
        // f_logqp = 0.5*sum(uu^2) = 2*sum((o+2y)^2)
        float fq = 0.f;
        float* yw = ys + ((size_t)(step + 1) * NTOT + n) * 20 + 5 * jg;
#pragma unroll
        for (int i = 0; i < 5; i++) {
            float od = o[5 * jg + i];
            float f  = od + yo[i];
            float uu = od + 2.f * yo[i];
            fq += uu * uu;
            yo[i] = yo[i] + f * dt + 0.5f * nz[i] * sdt;   // SIGMA = 0.5
            yw[i] = yo[i];
            s_y[(5 * jg + i) * 128 + pl] = yo[i];
        }
        fq += __shfl_xor_sync(0xffffffffu, fq, 1);
        fq += __shfl_xor_sync(0xffffffffu, fq, 2);
        lq += 2.f * fq * dt;
        if (jg == 0) {
            size_t idx = (size_t)(step + 1) * NTOT + n;
            size_t r = idx - 40;
            if (r % 41 == 0) lqout[r / 41] = lq;
        }
        __syncwarp();
    }
}

// ---------------------------------------------------------------------------
extern "C" void kernel_launch(void* const* d_in, const int* in_sizes, int n_in,
                              void* d_out, int out_size) {
    const float* z      = (const float*)d_in[0];
    const float* t      = (const float*)d_in[1];
    const float* Tx     = (const float*)d_in[2];
    const float* noise  = (const float*)d_in[3];
    const float* tw_in  = (const float*)d_in[4];
    const float* tb_in  = (const float*)d_in[5];
    const float* tw_h   = (const float*)d_in[6];
    const float* tb_h   = (const float*)d_in[7];
    const float* tw_out = (const float*)d_in[8];
    const float* tb_out = (const float*)d_in[9];
    const float* dw_in  = (const float*)d_in[10];
    const float* db_in  = (const float*)d_in[11];
    const float* dw_h   = (const float*)d_in[12];
    const float* db_h   = (const float*)d_in[13];
    const float* dw_out = (const float*)d_in[14];
    const float* db_out = (const float*)d_in[15];

    float* ys    = (float*)d_out;
    float* lqout = ys + (size_t)TLEN * NTOT * 20;

    const size_t smem_bytes = (size_t)SMEM_FLOATS * sizeof(float); // ~211 KB
    cudaFuncSetAttribute(sde_kernel, cudaFuncAttributeMaxDynamicSharedMemorySize,
                         (int)smem_bytes);

    sde_kernel<<<BLOCKS, THREADS, smem_bytes>>>(z, t, Tx, noise,
                                                tw_in, tb_in, tw_h, tb_h,
                                                tw_out, tb_out,
                                                dw_in, db_in, dw_h, db_h,
                                                dw_out, db_out, ys, lqout);
}

// round 5
// speedup vs baseline: 1.9156x; 1.9156x over previous
#include <cuda_runtime.h>
#include <math.h>

#define NTOT    16384
#define TLEN    41
#define NSTEP   40
#define THREADS 256
#define PPB     128          // particles per block (2 threads / particle)
#define BLOCKS  128

// ---- smem float offsets (weights k-major: adjacent j contiguous) ----
#define OFF_WIN  0                      // [24k][80j]
#define OFF_BIN  (OFF_WIN + 24*80)      // [80]            = 1920
#define OFF_WH   (OFF_BIN + 80)         // [4l][80k][80j]  = 2000
#define OFF_BH   (OFF_WH + 4*6400)      // [4][80]         = 27600
#define OFF_WOUT (OFF_BH + 320)         // [80k][20j]      = 27920
#define OFF_BOUT (OFF_WOUT + 1600)      // [20]            = 29520
#define OFF_U    (OFF_BOUT + 20)        // [40][4]         = 29540
#define OFF_Y    (OFF_U + 160)          // [20][128]       = 29700
#define OFF_HA   (OFF_Y + 20*128)       // [80][128]       = 32260
#define OFF_HB   (OFF_HA + 80*128)      // [80][128]       = 42500
#define SMEM_FLOATS (OFF_HB + 80*128)   // 52740 floats = 210960 B

typedef unsigned long long u64;

// packed f32x2 FMA (sm_100+): d = a*b + c per 32-bit lane
#define FMA2(d, a, b, c) \
    asm("fma.rn.f32x2 %0, %1, %2, %3;" : "=l"(d) : "l"(a), "l"(b), "l"(c))
#define PACK2(d, f) do { unsigned int _u = __float_as_uint(f); \
    asm("mov.b64 %0, {%1, %2};" : "=l"(d) : "r"(_u), "r"(_u)); } while (0)
#define UNPACK2(lo, hi, s) do { unsigned int _a, _b; \
    asm("mov.b64 {%0, %1}, %2;" : "=r"(_a), "=r"(_b) : "l"(s)); \
    lo = __uint_as_float(_a); hi = __uint_as_float(_b); } while (0)
#define TANHA(d, x) asm("tanh.approx.f32 %0, %1;" : "=f"(d) : "f"(x))

extern __shared__ float smem[];

__global__ void __launch_bounds__(THREADS, 1)
sde_kernel(const float* __restrict__ z, const float* __restrict__ t,
           const float* __restrict__ Tx, const float* __restrict__ noise,
           const float* __restrict__ tw_in, const float* __restrict__ tb_in,
           const float* __restrict__ tw_h,  const float* __restrict__ tb_h,
           const float* __restrict__ tw_out,const float* __restrict__ tb_out,
           const float* __restrict__ dw_in, const float* __restrict__ db_in,
           const float* __restrict__ dw_h,  const float* __restrict__ db_h,
           const float* __restrict__ dw_out,const float* __restrict__ db_out,
           float* __restrict__ ys, float* __restrict__ lqout) {
    float* s_win  = smem + OFF_WIN;
    float* s_bin  = smem + OFF_BIN;
    float* s_wh   = smem + OFF_WH;
    float* s_bh   = smem + OFF_BH;
    float* s_wout = smem + OFF_WOUT;
    float* s_bout = smem + OFF_BOUT;
    float* s_u    = smem + OFF_U;
    float* s_y    = smem + OFF_Y;
    float* s_hA   = smem + OFF_HA;
    float* s_hB   = smem + OFF_HB;

    const int tid = threadIdx.x;
    const int jh  = tid & 1;        // j-half: outputs [40jh, 40jh+40)
    const int pl  = tid >> 1;       // particle within block (0..127)

    // ---- cooperative load + transpose of drift weights into smem ----
    for (int idx = tid; idx < 24 * 80; idx += THREADS) {
        int j = idx / 24, k = idx % 24;
        s_win[k * 80 + j] = dw_in[idx];
    }
    for (int idx = tid; idx < 4 * 6400; idx += THREADS) {
        int l = idx / 6400, r = idx % 6400, j = r / 80, k = r % 80;
        s_wh[l * 6400 + k * 80 + j] = dw_h[idx];
    }
    for (int idx = tid; idx < 20 * 80; idx += THREADS) {
        int j = idx / 80, k = idx % 80;
        s_wout[k * 20 + j] = dw_out[idx];
    }
    // strided loops: valid for any THREADS (R4 bug was 512-thread guards here)
    for (int idx = tid; idx < 80;  idx += THREADS) s_bin[idx]  = db_in[idx];
    for (int idx = tid; idx < 320; idx += THREADS) s_bh[idx]   = db_h[idx];
    for (int idx = tid; idx < 20;  idx += THREADS) s_bout[idx] = db_out[idx];

    // ---- t-MLP fused: threads [192,232) compute u(t_i) -> s_u ----
    if (tid >= 192 && tid < 192 + NSTEP) {
        int i = tid - 192;
        float ti = t[i];
        float h[20], h2[20];
#pragma unroll
        for (int j = 0; j < 20; j++) h[j] = fmaxf(tw_in[j] * ti + tb_in[j], 0.f);
        for (int l = 0; l < 4; l++) {
            const float* w = tw_h + l * 400;
            const float* b = tb_h + l * 20;
#pragma unroll
            for (int j = 0; j < 20; j++) {
                float a = b[j];
#pragma unroll
                for (int k = 0; k < 20; k++) a += w[j * 20 + k] * h[k];
                h2[j] = fmaxf(a, 0.f);
            }
#pragma unroll
            for (int j = 0; j < 20; j++) h[j] = h2[j];
        }
#pragma unroll
        for (int c = 0; c < 4; c++) {
            float a = tb_out[c];
#pragma unroll
            for (int k = 0; k < 20; k++) a += tw_out[c * 20 + k] * h[k];
            s_u[i * 4 + c] = a;
        }
    }
    __syncthreads();

    const int n = blockIdx.x * PPB + pl;
    const float Tval = Tx[n >> 6];
    const float dt  = t[1] - t[0];
    const float sdt = sqrtf(dt);
    const int d0  = 10 * jh;                 // owned y-range [d0, d0+10)
    const int cA  = pl;                      // smem column, low row-group
    const int cB  = (pl + 16) & 127;         // smem column, high row-group
    const int cw  = jh ? cB : cA;            // column this thread writes

    // ---- particle state: this thread owns y[d0 .. d0+10) ----
    float yo[10];
    {
        const float2* zp = (const float2*)(z + (size_t)n * 20 + d0);
        float2* y0 = (float2*)(ys + (size_t)n * 20 + d0);
#pragma unroll
        for (int i = 0; i < 5; i++) {
            float2 v = zp[i];
            yo[2*i] = v.x; yo[2*i+1] = v.y;
            y0[i] = v;
            s_y[(d0 + 2*i)     * 128 + cw] = v.x;
            s_y[(d0 + 2*i + 1) * 128 + cw] = v.y;
        }
        if (jh == 0 && n >= 40 && (n - 40) % 41 == 0) lqout[(n - 40) / 41] = 0.f;
    }
    float lq = 0.f;
    __syncwarp();

    for (int step = 0; step < NSTEP; step++) {
        float ut[4];
#pragma unroll
        for (int c = 0; c < 4; c++) ut[c] = s_u[step * 4 + c] * Tval;

        // ======== input layer: [y(20), ut(4)] -> j in [40jh,40jh+40), relu
        {
            u64 acc[20];
            const ulonglong2* bv = (const ulonglong2*)(s_bin + 40 * jh);
#pragma unroll
            for (int q = 0; q < 10; q++) { ulonglong2 b = bv[q]; acc[2*q] = b.x; acc[2*q+1] = b.y; }
#pragma unroll 5
            for (int k = 0; k < 10; k++) {           // y[0..9] at column cA
                float xv = s_y[k * 128 + cA];
                u64 x2; PACK2(x2, xv);
                const ulonglong2* w = (const ulonglong2*)(s_win + k * 80 + 40 * jh);
#pragma unroll
                for (int q = 0; q < 10; q++) {
                    ulonglong2 wv = w[q];
                    FMA2(acc[2*q],   wv.x, x2, acc[2*q]);
                    FMA2(acc[2*q+1], wv.y, x2, acc[2*q+1]);
                }
            }
#pragma unroll 5
            for (int k = 10; k < 20; k++) {          // y[10..19] at column cB
                float xv = s_y[k * 128 + cB];
                u64 x2; PACK2(x2, xv);
                const ulonglong2* w = (const ulonglong2*)(s_win + k * 80 + 40 * jh);
#pragma unroll
                for (int q = 0; q < 10; q++) {
                    ulonglong2 wv = w[q];
                    FMA2(acc[2*q],   wv.x, x2, acc[2*q]);
                    FMA2(acc[2*q+1], wv.y, x2, acc[2*q+1]);
                }
            }
#pragma unroll
            for (int k = 20; k < 24; k++) {          // u_t inputs (registers)
                u64 x2; PACK2(x2, ut[k - 20]);
                const ulonglong2* w = (const ulonglong2*)(s_win + k * 80 + 40 * jh);
#pragma unroll
                for (int q = 0; q < 10; q++) {
                    ulonglong2 wv = w[q];
                    FMA2(acc[2*q],   wv.x, x2, acc[2*q]);
                    FMA2(acc[2*q+1], wv.y, x2, acc[2*q+1]);
                }
            }
            float* hw = s_hA + (40 * jh) * 128 + cw;
#pragma unroll
            for (int q = 0; q < 20; q++) {
                float a, b; UNPACK2(a, b, acc[q]);
                hw[(2*q)   * 128] = fmaxf(a, 0.f);
                hw[(2*q+1) * 128] = fmaxf(b, 0.f);
            }
        }
        __syncwarp();

        // ======== 4 hidden layers 80 -> 80, tanh.approx ========
        float* hin  = s_hA;
        float* hout = s_hB;
        for (int l = 0; l < 4; l++) {
            const float* wl = s_wh + l * 6400 + 40 * jh;
            u64 acc[20];
            const ulonglong2* bv = (const ulonglong2*)(s_bh + l * 80 + 40 * jh);
#pragma unroll
            for (int q = 0; q < 10; q++) { ulonglong2 b = bv[q]; acc[2*q] = b.x; acc[2*q+1] = b.y; }
#pragma unroll 4
            for (int k = 0; k < 40; k++) {           // rows 0..39 at column cA
                float hk = hin[k * 128 + cA];
                u64 h2; PACK2(h2, hk);
                const ulonglong2* w = (const ulonglong2*)(wl + k * 80);
#pragma unroll
                for (int q = 0; q < 10; q++) {
                    ulonglong2 wv = w[q];
                    FMA2(acc[2*q],   wv.x, h2, acc[2*q]);
                    FMA2(acc[2*q+1], wv.y, h2, acc[2*q+1]);
                }
            }
#pragma unroll 4
            for (int k = 40; k < 80; k++) {          // rows 40..79 at column cB
                float hk = hin[k * 128 + cB];
                u64 h2; PACK2(h2, hk);
                const ulonglong2* w = (const ulonglong2*)(wl + k * 80);
#pragma unroll
                for (int q = 0; q < 10; q++) {
                    ulonglong2 wv = w[q];
                    FMA2(acc[2*q],   wv.x, h2, acc[2*q]);
                    FMA2(acc[2*q+1], wv.y, h2, acc[2*q+1]);
                }
            }
            float* hw = hout + (40 * jh) * 128 + cw;
#pragma unroll
            for (int q = 0; q < 20; q++) {
                float a, b; UNPACK2(a, b, acc[q]);
                TANHA(a, a); TANHA(b, b);
                hw[(2*q)   * 128] = a;
                hw[(2*q+1) * 128] = b;
            }
            __syncwarp();
            float* tmp = hin; hin = hout; hout = tmp;
        }
        // final hidden is in hin (== s_hA after 4 swaps)

        // ---- prefetch noise (own 10 channels) ----
        float nz[10];
        {
            const float2* np2 = (const float2*)(noise + ((size_t)step * NTOT + n) * 22 + d0);
#pragma unroll
            for (int i = 0; i < 5; i++) {
                float2 v = np2[i];
                nz[2*i] = v.x; nz[2*i+1] = v.y;
            }
        }

        // ======== output layer 80 -> 20, k-split by jh ========
        float o[20];
        {
            u64 oc[10];
            const ulonglong2* bv = (const ulonglong2*)s_bout;
#pragma unroll
            for (int q = 0; q < 5; q++) {
                ulonglong2 b = bv[q];
                oc[2*q]   = (jh == 0) ? b.x : 0ull;
                oc[2*q+1] = (jh == 0) ? b.y : 0ull;
            }
            const float* hr = hin + (40 * jh) * 128 + cw;   // own k-range rows
#pragma unroll 4
            for (int kk = 0; kk < 40; kk++) {
                float hk = hr[kk * 128];
                u64 h2; PACK2(h2, hk);
                const ulonglong2* w = (const ulonglong2*)(s_wout + (40 * jh + kk) * 20);
#pragma unroll
                for (int q = 0; q < 5; q++) {
                    ulonglong2 wv = w[q];
                    FMA2(oc[2*q],   wv.x, h2, oc[2*q]);
                    FMA2(oc[2*q+1], wv.y, h2, oc[2*q+1]);
                }
            }
#pragma unroll
            for (int q = 0; q < 10; q++) UNPACK2(o[2*q], o[2*q+1], oc[q]);
            // pair exchange: each lane sends the partial its partner needs.
#pragma unroll
            for (int i = 0; i < 10; i++) {
                float v = o[10 * (1 - jh) + i];
                float p = __shfl_xor_sync(0xffffffffu, v, 1);
                o[d0 + i] += p;
            }
        }

        // ======== SDE update (own d-range [d0, d0+10)) ========
        // h = theta*(mu-y) = -y ; f = o + y ; uu = 2*(o + 2y)
        // f_logqp = 0.5*sum(uu^2) = 2*sum((o+2y)^2)
        float fq = 0.f;
        float2* yw = (float2*)(ys + ((size_t)(step + 1) * NTOT + n) * 20 + d0);
#pragma unroll
        for (int i = 0; i < 10; i++) {
            float od = o[d0 + i];
            float f  = od + yo[i];
            float uu = od + 2.f * yo[i];
            fq += uu * uu;
            yo[i] = yo[i] + f * dt + 0.5f * nz[i] * sdt;   // SIGMA = 0.5
            s_y[(d0 + i) * 128 + cw] = yo[i];
        }
#pragma unroll
        for (int i = 0; i < 5; i++) yw[i] = make_float2(yo[2*i], yo[2*i+1]);
        fq += __shfl_xor_sync(0xffffffffu, fq, 1);
        lq += 2.f * fq * dt;
        if (jh == 0) {
            size_t idx = (size_t)(step + 1) * NTOT + n;
            size_t r = idx - 40;
            if (r % 41 == 0) lqout[r / 41] = lq;
        }
        __syncwarp();
    }
}

// ---------------------------------------------------------------------------
extern "C" void kernel_launch(void* const* d_in, const int* in_sizes, int n_in,
                              void* d_out, int out_size) {
    const float* z      = (const float*)d_in[0];
    const float* t      = (const float*)d_in[1];
    const float* Tx     = (const float*)d_in[2];
    const float* noise  = (const float*)d_in[3];
    const float* tw_in  = (const float*)d_in[4];
    const float* tb_in  = (const float*)d_in[5];
    const float* tw_h   = (const float*)d_in[6];
    const float* tb_h   = (const float*)d_in[7];
    const float* tw_out = (const float*)d_in[8];
    const float* tb_out = (const float*)d_in[9];
    const float* dw_in  = (const float*)d_in[10];
    const float* db_in  = (const float*)d_in[11];
    const float* dw_h   = (const float*)d_in[12];
    const float* db_h   = (const float*)d_in[13];
    const float* dw_out = (const float*)d_in[14];
    const float* db_out = (const float*)d_in[15];

    float* ys    = (float*)d_out;
    float* lqout = ys + (size_t)TLEN * NTOT * 20;

    const size_t smem_bytes = (size_t)SMEM_FLOATS * sizeof(float); // ~211 KB
    cudaFuncSetAttribute(sde_kernel, cudaFuncAttributeMaxDynamicSharedMemorySize,
                         (int)smem_bytes);

    sde_kernel<<<BLOCKS, THREADS, smem_bytes>>>(z, t, Tx, noise,
                                                tw_in, tb_in, tw_h, tb_h,
                                                tw_out, tb_out,
                                                dw_in, db_in, dw_h, db_h,
                                                dw_out, db_out, ys, lqout);
}

// round 6
// speedup vs baseline: 2.7315x; 1.4259x over previous
#include <cuda_runtime.h>
#include <math.h>

#define NTOT    16384
#define TLEN    41
#define NSTEP   40
#define THREADS 256
#define PPB     128          // particles per block; 2 particles per thread
#define BLOCKS  128

// ---- smem float offsets ----
#define OFF_WIN  0            // [24k][80j]
#define OFF_BIN  1920         // [80]
#define OFF_WH   2000         // [4l][80k][80j]
#define OFF_BH   27600        // [4][80]
#define OFF_WOUT 27920        // [80k][20j]
#define OFF_BOUT 29520        // [20]
#define OFF_U    29540        // [40][4]
#define OFF_Y    29700        // [20][128] particle state
#define OFF_FQ   32260        // [4][128] fq partials
#define OFF_A    32772        // [80][128] activations A
#define OFF_B    43012        // [80][128] activations B
#define SMEM_FLOATS 53252     // 213,008 B

typedef unsigned long long u64;

#define FMA2(d, a, b, c) \
    asm("fma.rn.f32x2 %0, %1, %2, %3;" : "=l"(d) : "l"(a), "l"(b), "l"(c))
#define PACK2(d, f) do { unsigned int _u = __float_as_uint(f); \
    asm("mov.b64 %0, {%1, %2};" : "=l"(d) : "r"(_u), "r"(_u)); } while (0)
#define UNPACK2(lo, hi, s) do { unsigned int _a, _b; \
    asm("mov.b64 {%0, %1}, %2;" : "=r"(_a), "=r"(_b) : "l"(s)); \
    lo = __uint_as_float(_a); hi = __uint_as_float(_b); } while (0)
#define TANHA(d, x) asm("tanh.approx.f32 %0, %1;" : "=f"(d) : "f"(x))

extern __shared__ float smem[];

__global__ void __launch_bounds__(THREADS, 1)
sde_kernel(const float* __restrict__ z, const float* __restrict__ t,
           const float* __restrict__ Tx, const float* __restrict__ noise,
           const float* __restrict__ tw_in, const float* __restrict__ tb_in,
           const float* __restrict__ tw_h,  const float* __restrict__ tb_h,
           const float* __restrict__ tw_out,const float* __restrict__ tb_out,
           const float* __restrict__ dw_in, const float* __restrict__ db_in,
           const float* __restrict__ dw_h,  const float* __restrict__ db_h,
           const float* __restrict__ dw_out,const float* __restrict__ db_out,
           float* __restrict__ ys, float* __restrict__ lqout) {
    float* s_win  = smem + OFF_WIN;
    float* s_bin  = smem + OFF_BIN;
    float* s_wh   = smem + OFF_WH;
    float* s_bh   = smem + OFF_BH;
    float* s_wout = smem + OFF_WOUT;
    float* s_bout = smem + OFF_BOUT;
    float* s_u    = smem + OFF_U;
    float* s_y    = smem + OFF_Y;
    float* s_fq   = smem + OFF_FQ;
    float* s_A    = smem + OFF_A;
    float* s_B    = smem + OFF_B;

    const int tid  = threadIdx.x;
    const int jq   = tid >> 6;      // j-quarter 0..3 (uniform per warp-pair)
    const int pair = tid & 63;      // particle pair 0..63
    const int col0 = 2 * pair;      // smem column of particle 0 of the pair
    const int jb   = 20 * jq;       // j-base for MLP layers
    const int d0   = 5 * jq;        // owned state dims [d0, d0+5)

    // ---- cooperative load + transpose of drift weights into smem ----
    for (int idx = tid; idx < 24 * 80; idx += THREADS) {
        int j = idx / 24, k = idx % 24;
        s_win[k * 80 + j] = dw_in[idx];
    }
    for (int idx = tid; idx < 4 * 6400; idx += THREADS) {
        int l = idx / 6400, r = idx % 6400, j = r / 80, k = r % 80;
        s_wh[l * 6400 + k * 80 + j] = dw_h[idx];
    }
    for (int idx = tid; idx < 20 * 80; idx += THREADS) {
        int j = idx / 80, k = idx % 80;
        s_wout[k * 20 + j] = dw_out[idx];
    }
    for (int idx = tid; idx < 80;  idx += THREADS) s_bin[idx]  = db_in[idx];
    for (int idx = tid; idx < 320; idx += THREADS) s_bh[idx]   = db_h[idx];
    for (int idx = tid; idx < 20;  idx += THREADS) s_bout[idx] = db_out[idx];

    // ---- t-MLP fused: threads [192,232) compute u(t_i) -> s_u ----
    if (tid >= 192 && tid < 192 + NSTEP) {
        int i = tid - 192;
        float ti = t[i];
        float h[20], h2[20];
#pragma unroll
        for (int j = 0; j < 20; j++) h[j] = fmaxf(tw_in[j] * ti + tb_in[j], 0.f);
        for (int l = 0; l < 4; l++) {
            const float* w = tw_h + l * 400;
            const float* b = tb_h + l * 20;
#pragma unroll
            for (int j = 0; j < 20; j++) {
                float a = b[j];
#pragma unroll
                for (int k = 0; k < 20; k++) a += w[j * 20 + k] * h[k];
                h2[j] = fmaxf(a, 0.f);
            }
#pragma unroll
            for (int j = 0; j < 20; j++) h[j] = h2[j];
        }
#pragma unroll
        for (int c = 0; c < 4; c++) {
            float a = tb_out[c];
#pragma unroll
            for (int k = 0; k < 20; k++) a += tw_out[c * 20 + k] * h[k];
            s_u[i * 4 + c] = a;
        }
    }

    const int n0 = blockIdx.x * PPB + col0;   // particle 0; particle 1 = n0+1
    const float Tval = Tx[n0 >> 6];           // same for n0 and n0+1 (n0 even)
    const float dt  = t[1] - t[0];
    const float sdt = sqrtf(dt);

    // ---- init: own dims of both particles ----
    float y0[5], y1[5];
#pragma unroll
    for (int i = 0; i < 5; i++) {
        y0[i] = z[(size_t)n0 * 20 + d0 + i];
        y1[i] = z[(size_t)(n0 + 1) * 20 + d0 + i];
        *(float2*)(s_y + (d0 + i) * 128 + col0) = make_float2(y0[i], y1[i]);
        ys[(size_t)n0 * 20 + d0 + i]       = y0[i];
        ys[(size_t)(n0 + 1) * 20 + d0 + i] = y1[i];
    }
    float lq0 = 0.f, lq1 = 0.f;
    if (jq == 0) {
        if (n0 >= 40 && (n0 - 40) % 41 == 0) lqout[(n0 - 40) / 41] = 0.f;
        int n1 = n0 + 1;
        if (n1 >= 40 && (n1 - 40) % 41 == 0) lqout[(n1 - 40) / 41] = 0.f;
    }
    __syncthreads();

    for (int step = 0; step < NSTEP; step++) {
        float ut[4];
#pragma unroll
        for (int c = 0; c < 4; c++) ut[c] = s_u[step * 4 + c] * Tval;

        // ======== input layer: [y(20), ut(4)] -> j in [jb, jb+20), relu ====
        {
            u64 a0[10], a1[10];
            const ulonglong2* bv = (const ulonglong2*)(s_bin + jb);
#pragma unroll
            for (int q = 0; q < 5; q++) {
                ulonglong2 b = bv[q];
                a0[2*q] = b.x; a0[2*q+1] = b.y;
                a1[2*q] = b.x; a1[2*q+1] = b.y;
            }
#pragma unroll 5
            for (int k = 0; k < 20; k++) {
                float2 yk = *(const float2*)(s_y + k * 128 + col0);
                u64 x0, x1; PACK2(x0, yk.x); PACK2(x1, yk.y);
                const ulonglong2* w = (const ulonglong2*)(s_win + k * 80 + jb);
#pragma unroll
                for (int q = 0; q < 5; q++) {
                    ulonglong2 wv = w[q];
                    FMA2(a0[2*q],   wv.x, x0, a0[2*q]);
                    FMA2(a0[2*q+1], wv.y, x0, a0[2*q+1]);
                    FMA2(a1[2*q],   wv.x, x1, a1[2*q]);
                    FMA2(a1[2*q+1], wv.y, x1, a1[2*q+1]);
                }
            }
#pragma unroll
            for (int k = 20; k < 24; k++) {     // ut same for both particles
                u64 xu; PACK2(xu, ut[k - 20]);
                const ulonglong2* w = (const ulonglong2*)(s_win + k * 80 + jb);
#pragma unroll
                for (int q = 0; q < 5; q++) {
                    ulonglong2 wv = w[q];
                    FMA2(a0[2*q],   wv.x, xu, a0[2*q]);
                    FMA2(a0[2*q+1], wv.y, xu, a0[2*q+1]);
                    FMA2(a1[2*q],   wv.x, xu, a1[2*q]);
                    FMA2(a1[2*q+1], wv.y, xu, a1[2*q+1]);
                }
            }
            float* hw = s_A + jb * 128 + col0;
#pragma unroll
            for (int q = 0; q < 10; q++) {
                float p0a, p0b, p1a, p1b;
                UNPACK2(p0a, p0b, a0[q]);
                UNPACK2(p1a, p1b, a1[q]);
                *(float2*)(hw + (2*q)   * 128) = make_float2(fmaxf(p0a, 0.f), fmaxf(p1a, 0.f));
                *(float2*)(hw + (2*q+1) * 128) = make_float2(fmaxf(p0b, 0.f), fmaxf(p1b, 0.f));
            }
        }
        __syncthreads();

        // ======== 4 hidden layers 80 -> 80, tanh.approx ========
        float* hin  = s_A;
        float* hout = s_B;
        for (int l = 0; l < 4; l++) {
            const float* wl = s_wh + l * 6400 + jb;
            u64 a0[10], a1[10];
            const ulonglong2* bv = (const ulonglong2*)(s_bh + l * 80 + jb);
#pragma unroll
            for (int q = 0; q < 5; q++) {
                ulonglong2 b = bv[q];
                a0[2*q] = b.x; a0[2*q+1] = b.y;
                a1[2*q] = b.x; a1[2*q+1] = b.y;
            }
#pragma unroll 10
            for (int k = 0; k < 80; k++) {
                float2 hk = *(const float2*)(hin + k * 128 + col0);
                u64 x0, x1; PACK2(x0, hk.x); PACK2(x1, hk.y);
                const ulonglong2* w = (const ulonglong2*)(wl + k * 80);
#pragma unroll
                for (int q = 0; q < 5; q++) {
                    ulonglong2 wv = w[q];
                    FMA2(a0[2*q],   wv.x, x0, a0[2*q]);
                    FMA2(a0[2*q+1], wv.y, x0, a0[2*q+1]);
                    FMA2(a1[2*q],   wv.x, x1, a1[2*q]);
                    FMA2(a1[2*q+1], wv.y, x1, a1[2*q+1]);
                }
            }
            float* hw = hout + jb * 128 + col0;
#pragma unroll
            for (int q = 0; q < 10; q++) {
                float p0a, p0b, p1a, p1b;
                UNPACK2(p0a, p0b, a0[q]);
                UNPACK2(p1a, p1b, a1[q]);
                TANHA(p0a, p0a); TANHA(p0b, p0b);
                TANHA(p1a, p1a); TANHA(p1b, p1b);
                *(float2*)(hw + (2*q)   * 128) = make_float2(p0a, p1a);
                *(float2*)(hw + (2*q+1) * 128) = make_float2(p0b, p1b);
            }
            __syncthreads();
            float* tmp = hin; hin = hout; hout = tmp;
        }
        // after 4 swaps: hin == s_A (final hidden), hout == s_B (free)

        // ---- prefetch noise (own 5 dims x 2 particles) ----
        float nz0[5], nz1[5];
        {
            const float* np0 = noise + ((size_t)step * NTOT + n0) * 22 + d0;
            const float* np1 = np0 + 22;
#pragma unroll
            for (int i = 0; i < 5; i++) { nz0[i] = np0[i]; nz1[i] = np1[i]; }
        }

        // ======== output layer: k in [jb, jb+20), partials for all 20 j ====
        {
            u64 o0[10], o1[10];
#pragma unroll
            for (int q = 0; q < 10; q++) { o0[q] = 0ull; o1[q] = 0ull; }
#pragma unroll 10
            for (int kk = 0; kk < 20; kk++) {
                float2 hk = *(const float2*)(hin + (jb + kk) * 128 + col0);
                u64 x0, x1; PACK2(x0, hk.x); PACK2(x1, hk.y);
                const ulonglong2* w = (const ulonglong2*)(s_wout + (jb + kk) * 20);
#pragma unroll
                for (int q = 0; q < 5; q++) {
                    ulonglong2 wv = w[q];
                    FMA2(o0[2*q],   wv.x, x0, o0[2*q]);
                    FMA2(o0[2*q+1], wv.y, x0, o0[2*q+1]);
                    FMA2(o1[2*q],   wv.x, x1, o1[2*q]);
                    FMA2(o1[2*q+1], wv.y, x1, o1[2*q+1]);
                }
            }
            // write partials: row = jq*20 + j, col = particle column
            float* pw = hout + (jq * 20) * 128 + col0;
#pragma unroll
            for (int q = 0; q < 10; q++) {
                float p0a, p0b, p1a, p1b;
                UNPACK2(p0a, p0b, o0[q]);
                UNPACK2(p1a, p1b, o1[q]);
                *(float2*)(pw + (2*q)   * 128) = make_float2(p0a, p1a);
                *(float2*)(pw + (2*q+1) * 128) = make_float2(p0b, p1b);
            }
        }
        __syncthreads();

        // ======== reduce partials + SDE update (own dims [d0, d0+5)) ======
        // h = -y ; f = o + y ; uu = 2(o + 2y) ; f_logqp = 2*sum((o+2y)^2)
        {
            float fq0 = 0.f, fq1 = 0.f;
            float* ywp0 = ys + ((size_t)(step + 1) * NTOT + n0) * 20 + d0;
            float* ywp1 = ywp0 + 20;
#pragma unroll
            for (int i = 0; i < 5; i++) {
                int j = d0 + i;
                float s0 = s_bout[j], s1 = s0;
#pragma unroll
                for (int g = 0; g < 4; g++) {
                    float2 p = *(const float2*)(hout + (g * 20 + j) * 128 + col0);
                    s0 += p.x; s1 += p.y;
                }
                float f0 = s0 + y0[i], uu0 = s0 + 2.f * y0[i];
                float f1 = s1 + y1[i], uu1 = s1 + 2.f * y1[i];
                fq0 += uu0 * uu0; fq1 += uu1 * uu1;
                y0[i] = y0[i] + f0 * dt + 0.5f * nz0[i] * sdt;  // SIGMA = 0.5
                y1[i] = y1[i] + f1 * dt + 0.5f * nz1[i] * sdt;
                *(float2*)(s_y + j * 128 + col0) = make_float2(y0[i], y1[i]);
                ywp0[i] = y0[i];
                ywp1[i] = y1[i];
            }
            *(float2*)(s_fq + jq * 128 + col0) = make_float2(fq0, fq1);
        }
        __syncthreads();

        // jq0 owns logqp bookkeeping (reads s_fq written before the barrier;
        // s_fq is not overwritten until after next step's 6th barrier)
        if (jq == 0) {
            float f0t = 0.f, f1t = 0.f;
#pragma unroll
            for (int g = 0; g < 4; g++) {
                float2 p = *(const float2*)(s_fq + g * 128 + col0);
                f0t += p.x; f1t += p.y;
            }
            lq0 += 2.f * f0t * dt;
            lq1 += 2.f * f1t * dt;
            size_t idx0 = (size_t)(step + 1) * NTOT + n0;
            size_t r0 = idx0 - 40;
            if (r0 % 41 == 0) lqout[r0 / 41] = lq0;
            size_t r1 = idx0 + 1 - 40;
            if (r1 % 41 == 0) lqout[r1 / 41] = lq1;
        }
    }
}

// ---------------------------------------------------------------------------
extern "C" void kernel_launch(void* const* d_in, const int* in_sizes, int n_in,
                              void* d_out, int out_size) {
    const float* z      = (const float*)d_in[0];
    const float* t      = (const float*)d_in[1];
    const float* Tx     = (const float*)d_in[2];
    const float* noise  = (const float*)d_in[3];
    const float* tw_in  = (const float*)d_in[4];
    const float* tb_in  = (const float*)d_in[5];
    const float* tw_h   = (const float*)d_in[6];
    const float* tb_h   = (const float*)d_in[7];
    const float* tw_out = (const float*)d_in[8];
    const float* tb_out = (const float*)d_in[9];
    const float* dw_in  = (const float*)d_in[10];
    const float* db_in  = (const float*)d_in[11];
    const float* dw_h   = (const float*)d_in[12];
    const float* db_h   = (const float*)d_in[13];
    const float* dw_out = (const float*)d_in[14];
    const float* db_out = (const float*)d_in[15];

    float* ys    = (float*)d_out;
    float* lqout = ys + (size_t)TLEN * NTOT * 20;

    const size_t smem_bytes = (size_t)SMEM_FLOATS * sizeof(float); // ~213 KB
    cudaFuncSetAttribute(sde_kernel, cudaFuncAttributeMaxDynamicSharedMemorySize,
                         (int)smem_bytes);

    sde_kernel<<<BLOCKS, THREADS, smem_bytes>>>(z, t, Tx, noise,
                                                tw_in, tb_in, tw_h, tb_h,
                                                tw_out, tb_out,
                                                dw_in, db_in, dw_h, db_h,
                                                dw_out, db_out, ys, lqout);
}